// round 3
// baseline (speedup 1.0000x reference)
#include <cuda_runtime.h>
#include <cuda_bf16.h>
#include <cstdint>
#include <math.h>

// ================= problem constants =================
static constexpr int CIN = 16, HI = 256, WI = 256;
static constexpr int OH = 254, OW = 254;
static constexpr int TH = 16;              // output rows per CTA
static constexpr int PR = TH + 2;          // staged input rows = 18
static constexpr int PW = 132;             // staged input cols: 128 + 2 halo + 2 pad (bank perm)
static constexpr int PLANE = PR * PW;      // 2376 words; 2376 % 32 == 8 -> conflict-free A reads
static constexpr int BSTR = 72;            // B n-stride; 72 % 32 == 8 -> conflict-free B reads

// smem offsets in 32-bit words
static constexpr int W_B     = 0;                  // 9*8*72 = 5184 words
static constexpr int W_BIAS  = 5184;               // 64 words
static constexpr int W_IN    = 5248;               // 8 planes * 2376 = 19008 words
static constexpr int SMEM_WORDS = W_IN + 8 * PLANE;        // 24256
static constexpr int SMEM_BYTES = SMEM_WORDS * 4;          // 97024

#define MMA16816(cc, aa, bb0, bb1)                                              \
    asm volatile(                                                               \
        "mma.sync.aligned.m16n8k16.row.col.f32.bf16.bf16.f32 "                  \
        "{%0,%1,%2,%3}, {%4,%5,%6,%7}, {%8,%9}, {%0,%1,%2,%3};"                 \
        : "+f"((cc)[0]), "+f"((cc)[1]), "+f"((cc)[2]), "+f"((cc)[3])            \
        : "r"((aa)[0]), "r"((aa)[1]), "r"((aa)[2]), "r"((aa)[3]),               \
          "r"(bb0), "r"(bb1))

__global__ void __launch_bounds__(256, 2)
conv_min_tanh_mma(const float* __restrict__ xg, const float* __restrict__ wp,
                  const float* __restrict__ bp, float* __restrict__ outp)
{
    extern __shared__ uint32_t sm[];
    uint32_t* Bsm     = sm + W_B;
    float*    bias_sm = reinterpret_cast<float*>(sm + W_BIAS);
    uint32_t* planes  = sm + W_IN;

    const int tid = threadIdx.x;
    const int x0  = blockIdx.x ? (OW - 128) : 0;   // 0 or 126; 2-col overlap recomputed identically
    const int y0  = blockIdx.y * TH;
    const int b   = blockIdx.z;

    // ---- B operand: Bsm[(pos*8 + j)*BSTR + n] = bf16x2(w[n][2j][pos], w[n][2j+1][pos]) ----
    for (int i = tid; i < 9 * 8 * 64; i += 256) {
        int n   = i & 63;
        int pj  = i >> 6;            // 0..71 = pos*8 + j
        int pos = pj >> 3, j = pj & 7;
        float lo = wp[n * 144 + (2 * j) * 9 + pos];
        float hi = wp[n * 144 + (2 * j + 1) * 9 + pos];
        __nv_bfloat162 v = __floats2bfloat162_rn(lo, hi);
        Bsm[pj * BSTR + n] = *reinterpret_cast<uint32_t*>(&v);
    }
    if (tid < 64) bias_sm[tid] = bp[tid];

    // ---- input tile -> 8 cin-pair planes of bf16x2 ----
    const float* xb = xg + (size_t)b * (CIN * HI * WI);
    for (int i = tid; i < 8 * PR * 130; i += 256) {
        int j   = i / (PR * 130);
        int rem = i - j * (PR * 130);
        int r   = rem / 130;
        int c   = rem - r * 130;
        int yin = y0 + r;
        if (yin < HI) {
            const float* p0 = xb + (size_t)(2 * j) * (HI * WI) + yin * WI + x0 + c;
            __nv_bfloat162 v = __floats2bfloat162_rn(p0[0], p0[HI * WI]);
            planes[j * PLANE + r * PW + c] = *reinterpret_cast<uint32_t*>(&v);
        }
    }
    __syncthreads();

    const int wid  = tid >> 5;
    const int lane = tid & 31;
    const int tg   = lane & 3;     // threadID_in_group
    const int gid  = lane >> 2;    // groupID

    // per-lane bias for accumulator init: C cols n = nt*8 + tg*2 (+1)
    float bias0[8], bias1[8];
    #pragma unroll
    for (int nt = 0; nt < 8; nt++) {
        bias0[nt] = bias_sm[nt * 8 + tg * 2];
        bias1[nt] = bias_sm[nt * 8 + tg * 2 + 1];
    }

    // 64 double-tiles: d -> row t = d>>2, col-segment pair (2*(d&3), 2*(d&3)+1)
    for (int d = wid; d < 64; d += 8) {
        const int t = d >> 2;
        const int y = y0 + t;
        if (y >= OH) continue;
        const int cb0 = (d & 3) * 32;    // seg s0 = 2*(d&3), 16 px each
        const int cb1 = cb0 + 16;

        float c[2][8][4];
        #pragma unroll
        for (int nt = 0; nt < 8; nt++) {
            c[0][nt][0] = c[0][nt][2] = bias0[nt];
            c[0][nt][1] = c[0][nt][3] = bias1[nt];
            c[1][nt][0] = c[1][nt][2] = bias0[nt];
            c[1][nt][1] = c[1][nt][3] = bias1[nt];
        }

        #pragma unroll
        for (int dy = 0; dy < 3; dy++) {
            #pragma unroll
            for (int dx = 0; dx < 3; dx++) {
                const int pos = dy * 3 + dx;
                // A fragments: a0/a1 from plane tg (k-pairs 0-3), a2/a3 from plane tg+4
                const uint32_t* pl0 = planes + tg * PLANE + (t + dy) * PW + dx;
                const uint32_t* pl4 = pl0 + 4 * PLANE;
                uint32_t a[2][4];
                a[0][0] = pl0[cb0 + gid];      // row gid,   k 2tg..2tg+1
                a[0][1] = pl0[cb0 + gid + 8];  // row gid+8
                a[0][2] = pl4[cb0 + gid];      // row gid,   k 2tg+8..9
                a[0][3] = pl4[cb0 + gid + 8];
                a[1][0] = pl0[cb1 + gid];
                a[1][1] = pl0[cb1 + gid + 8];
                a[1][2] = pl4[cb1 + gid];
                a[1][3] = pl4[cb1 + gid + 8];

                const uint32_t* bq0 = Bsm + (pos * 8 + tg) * BSTR + gid;  // b0: pair tg
                const uint32_t* bq1 = bq0 + 4 * BSTR;                     // b1: pair tg+4
                #pragma unroll
                for (int nt = 0; nt < 8; nt++) {
                    const uint32_t b0 = bq0[nt * 8];
                    const uint32_t b1 = bq1[nt * 8];
                    MMA16816(c[0][nt], a[0], b0, b1);
                    MMA16816(c[1][nt], a[1], b0, b1);
                }
            }
        }

        // epilogue: min over n (16 local values -> quad shuffle), tanh(tanh), store
        #pragma unroll
        for (int ti = 0; ti < 2; ti++) {
            float lo = fminf(c[ti][0][0], c[ti][0][1]);
            float hi = fminf(c[ti][0][2], c[ti][0][3]);
            #pragma unroll
            for (int nt = 1; nt < 8; nt++) {
                lo = fminf(lo, fminf(c[ti][nt][0], c[ti][nt][1]));
                hi = fminf(hi, fminf(c[ti][nt][2], c[ti][nt][3]));
            }
            lo = fminf(lo, __shfl_xor_sync(0xFFFFFFFFu, lo, 1));
            lo = fminf(lo, __shfl_xor_sync(0xFFFFFFFFu, lo, 2));
            hi = fminf(hi, __shfl_xor_sync(0xFFFFFFFFu, hi, 1));
            hi = fminf(hi, __shfl_xor_sync(0xFFFFFFFFu, hi, 2));
            if (tg == 0) {
                const int cb = ti ? cb1 : cb0;
                float vlo = tanhf(tanhf(lo));
                float vhi = tanhf(tanhf(hi));
                float* orow = outp + ((size_t)b * OH + y) * OW + x0 + cb;
                orow[gid]     = vlo;   // pixel row gid
                orow[gid + 8] = vhi;   // pixel row gid+8
            }
        }
    }
}

// ================= launch =================
extern "C" void kernel_launch(void* const* d_in, const int* in_sizes, int n_in,
                              void* d_out, int out_size) {
    (void)in_sizes; (void)n_in; (void)out_size;
    const float* x    = (const float*)d_in[0];
    const float* w    = (const float*)d_in[1];
    const float* bias = (const float*)d_in[2];
    float* out = (float*)d_out;

    cudaFuncSetAttribute(conv_min_tanh_mma,
                         cudaFuncAttributeMaxDynamicSharedMemorySize, SMEM_BYTES);
    dim3 grid(2, 16, 64);   // x: two 128-col halves; y: 16-row tiles; z: batch
    conv_min_tanh_mma<<<grid, 256, SMEM_BYTES>>>(x, w, bias, out);
}

// round 4
// speedup vs baseline: 1.2851x; 1.2851x over previous
#include <cuda_runtime.h>
#include <cuda_fp16.h>
#include <cstdint>
#include <math.h>

// ================= problem constants =================
static constexpr int CIN = 16, HI = 256, WI = 256;
static constexpr int OH = 254, OW = 254;
static constexpr int TH = 16;              // output rows per CTA
static constexpr int PR = TH + 2;          // staged input rows = 18
static constexpr int PW = 132;             // staged cols: 128 + 2 halo + 2 pad (bank perm)
static constexpr int PLANE = PR * PW;      // 2376 words; 2376 % 32 == 8 -> conflict-free A reads
static constexpr int BSTR = 72;            // B n-stride; 72 % 32 == 8 -> conflict-free B reads

// smem offsets in 32-bit words
static constexpr int W_B     = 0;                   // 9*8*72 = 5184 words (half2 each)
static constexpr int W_BIAS  = 5184;                // 32 words: bias_h2[nt*4+tg]
static constexpr int W_IN    = 5216;                // 8 planes * 2376 words (half2 each)
static constexpr int SMEM_WORDS = W_IN + 8 * PLANE;         // 24224
static constexpr int SMEM_BYTES = SMEM_WORDS * 4;           // 96896

// f16 in, f16 accumulate: 2x legacy-tensor rate, half the accumulator regs
#define MMA16816H(cc, aa, bb0, bb1)                                             \
    asm volatile(                                                               \
        "mma.sync.aligned.m16n8k16.row.col.f16.f16.f16.f16 "                    \
        "{%0,%1}, {%2,%3,%4,%5}, {%6,%7}, {%0,%1};"                             \
        : "+r"((cc)[0]), "+r"((cc)[1])                                          \
        : "r"((aa)[0]), "r"((aa)[1]), "r"((aa)[2]), "r"((aa)[3]),               \
          "r"(bb0), "r"(bb1))

__global__ void __launch_bounds__(384, 2)
conv_min_tanh_mma(const float* __restrict__ xg, const float* __restrict__ wp,
                  const float* __restrict__ bp, float* __restrict__ outp)
{
    extern __shared__ uint32_t sm[];
    uint32_t* Bsm     = sm + W_B;
    uint32_t* bias_sm = sm + W_BIAS;
    uint32_t* planes  = sm + W_IN;

    const int tid = threadIdx.x;
    const int x0  = blockIdx.x ? (OW - 128) : 0;   // 0 or 126; 2-col overlap recomputed identically
    const int y0  = blockIdx.y * TH;
    const int b   = blockIdx.z;

    // ---- B operand: Bsm[(pos*8 + j)*BSTR + n] = half2(w[n][2j][pos], w[n][2j+1][pos]) ----
    for (int i = tid; i < 9 * 8 * 64; i += 384) {
        int n   = i & 63;
        int pj  = i >> 6;            // 0..71 = pos*8 + j
        int pos = pj >> 3, j = pj & 7;
        float lo = wp[n * 144 + (2 * j) * 9 + pos];
        float hi = wp[n * 144 + (2 * j + 1) * 9 + pos];
        __half2 v = __floats2half2_rn(lo, hi);
        Bsm[pj * BSTR + n] = *reinterpret_cast<uint32_t*>(&v);
    }
    // bias pre-packed per (nt, tg): cols (nt*8 + 2tg, nt*8 + 2tg + 1)
    if (tid < 32) {
        int nt = tid >> 2, tg = tid & 3;
        __half2 v = __floats2half2_rn(bp[nt * 8 + 2 * tg], bp[nt * 8 + 2 * tg + 1]);
        bias_sm[tid] = *reinterpret_cast<uint32_t*>(&v);
    }

    // ---- input tile -> 8 cin-pair planes of half2 ----
    const float* xb = xg + (size_t)b * (CIN * HI * WI);
    for (int i = tid; i < 8 * PR * 130; i += 384) {
        int j   = i / (PR * 130);
        int rem = i - j * (PR * 130);
        int r   = rem / 130;
        int c   = rem - r * 130;
        int yin = y0 + r;
        if (yin < HI) {
            const float* p0 = xb + (size_t)(2 * j) * (HI * WI) + yin * WI + x0 + c;
            __half2 v = __floats2half2_rn(p0[0], p0[HI * WI]);
            planes[j * PLANE + r * PW + c] = *reinterpret_cast<uint32_t*>(&v);
        }
    }
    __syncthreads();

    const int wid  = tid >> 5;
    const int lane = tid & 31;
    const int tg   = lane & 3;     // threadID_in_group
    const int gid  = lane >> 2;    // groupID

    // 64 double-tiles: d -> row t = d>>2, col-segment pair base (d&3)*32
    for (int d = wid; d < 64; d += 12) {
        const int t = d >> 2;
        const int y = y0 + t;
        if (y >= OH) continue;
        const int cb0 = (d & 3) * 32;    // two 16-px segments: cb0, cb0+16
        const int cb1 = cb0 + 16;

        // accumulators: c[tile][nt][{rows gid, rows gid+8}] as half2 (cols 2tg, 2tg+1)
        uint32_t c[2][8][2];
        #pragma unroll
        for (int nt = 0; nt < 8; nt++) {
            uint32_t bv = bias_sm[nt * 4 + tg];
            c[0][nt][0] = bv; c[0][nt][1] = bv;
            c[1][nt][0] = bv; c[1][nt][1] = bv;
        }

        #pragma unroll
        for (int dy = 0; dy < 3; dy++) {
            #pragma unroll
            for (int dx = 0; dx < 3; dx++) {
                const int pos = dy * 3 + dx;
                // A: a0/a1 from plane tg (k 2tg..2tg+1), a2/a3 from plane tg+4
                const uint32_t* pl0 = planes + tg * PLANE + (t + dy) * PW + dx;
                const uint32_t* pl4 = pl0 + 4 * PLANE;
                uint32_t a[2][4];
                a[0][0] = pl0[cb0 + gid];
                a[0][1] = pl0[cb0 + gid + 8];
                a[0][2] = pl4[cb0 + gid];
                a[0][3] = pl4[cb0 + gid + 8];
                a[1][0] = pl0[cb1 + gid];
                a[1][1] = pl0[cb1 + gid + 8];
                a[1][2] = pl4[cb1 + gid];
                a[1][3] = pl4[cb1 + gid + 8];

                const uint32_t* bq0 = Bsm + (pos * 8 + tg) * BSTR + gid;  // b0: k-pair tg
                const uint32_t* bq1 = bq0 + 4 * BSTR;                     // b1: k-pair tg+4
                #pragma unroll
                for (int nt = 0; nt < 8; nt++) {
                    const uint32_t b0 = bq0[nt * 8];
                    const uint32_t b1 = bq1[nt * 8];
                    MMA16816H(c[0][nt], a[0], b0, b1);
                    MMA16816H(c[1][nt], a[1], b0, b1);
                }
            }
        }

        // epilogue: min over 64 couts (8 nt packed-min -> quad shuffle -> halves), tanh^2
        #pragma unroll
        for (int ti = 0; ti < 2; ti++) {
            __half2 mlo = *reinterpret_cast<__half2*>(&c[ti][0][0]);  // rows gid
            __half2 mhi = *reinterpret_cast<__half2*>(&c[ti][0][1]);  // rows gid+8
            #pragma unroll
            for (int nt = 1; nt < 8; nt++) {
                mlo = __hmin2(mlo, *reinterpret_cast<__half2*>(&c[ti][nt][0]));
                mhi = __hmin2(mhi, *reinterpret_cast<__half2*>(&c[ti][nt][1]));
            }
            uint32_t ulo = *reinterpret_cast<uint32_t*>(&mlo);
            uint32_t uhi = *reinterpret_cast<uint32_t*>(&mhi);
            // min across the quad (tg dimension carries cols 2tg,2tg+1)
            uint32_t s;
            s = __shfl_xor_sync(0xFFFFFFFFu, ulo, 1);
            mlo = __hmin2(*reinterpret_cast<__half2*>(&ulo), *reinterpret_cast<__half2*>(&s));
            ulo = *reinterpret_cast<uint32_t*>(&mlo);
            s = __shfl_xor_sync(0xFFFFFFFFu, ulo, 2);
            mlo = __hmin2(*reinterpret_cast<__half2*>(&ulo), *reinterpret_cast<__half2*>(&s));
            s = __shfl_xor_sync(0xFFFFFFFFu, uhi, 1);
            mhi = __hmin2(*reinterpret_cast<__half2*>(&uhi), *reinterpret_cast<__half2*>(&s));
            uhi = *reinterpret_cast<uint32_t*>(&mhi);
            s = __shfl_xor_sync(0xFFFFFFFFu, uhi, 2);
            mhi = __hmin2(*reinterpret_cast<__half2*>(&uhi), *reinterpret_cast<__half2*>(&s));

            if (tg == 0) {
                float vlo = fminf(__low2float(mlo), __high2float(mlo));
                float vhi = fminf(__low2float(mhi), __high2float(mhi));
                vlo = tanhf(tanhf(vlo));
                vhi = tanhf(tanhf(vhi));
                const int cb = ti ? cb1 : cb0;
                float* orow = outp + ((size_t)b * OH + y) * OW + x0 + cb;
                orow[gid]     = vlo;   // pixel row gid
                orow[gid + 8] = vhi;   // pixel row gid+8
            }
        }
    }
}

// ================= launch =================
extern "C" void kernel_launch(void* const* d_in, const int* in_sizes, int n_in,
                              void* d_out, int out_size) {
    (void)in_sizes; (void)n_in; (void)out_size;
    const float* x    = (const float*)d_in[0];
    const float* w    = (const float*)d_in[1];
    const float* bias = (const float*)d_in[2];
    float* out = (float*)d_out;

    cudaFuncSetAttribute(conv_min_tanh_mma,
                         cudaFuncAttributeMaxDynamicSharedMemorySize, SMEM_BYTES);
    dim3 grid(2, 16, 64);   // x: two 128-col halves; y: 16-row tiles; z: batch
    conv_min_tanh_mma<<<grid, 384, SMEM_BYTES>>>(x, w, bias, out);
}

// round 5
// speedup vs baseline: 1.8713x; 1.4562x over previous
#include <cuda_runtime.h>
#include <cuda_fp16.h>
#include <cstdint>
#include <math.h>

// ================= problem constants =================
static constexpr int CIN = 16, HI = 256, WI = 256;
static constexpr int OH = 254, OW = 254;
static constexpr int TH = 16;              // output rows per CTA
static constexpr int PR = TH + 2;          // staged input rows = 18
static constexpr int PW = 130;             // staged input cols: 128 + 2 halo
// Interleaved A layout: word = (r*PW + c)*8 + slot, slot order {0,4,1,5,2,6,3,7}
// (plane j<4 -> slot 2j ; plane j>=4 -> slot 2j-7). Lane (gid,tg) LDS.64 at
// pix*8 + 2*tg  -> (k-pair tg, k-pair tg+4). Banks 8*(pix%4)+2tg: conflict-free
// per half-warp.
// Interleaved B layout: word = (pos*64 + n)*8 + slot (same slot order).

// smem offsets in 32-bit words
static constexpr int W_B     = 0;                   // 9*64*8 = 4608 words
static constexpr int W_BIAS  = 4608;                // 32 words: bias_h2[nt*4+tg]
static constexpr int W_IN    = 4640;                // PR*PW*8 = 18720 words
static constexpr int SMEM_WORDS = W_IN + PR * PW * 8;       // 23360
static constexpr int SMEM_BYTES = SMEM_WORDS * 4;           // 93440

// f16 in, f16 accumulate
#define MMA16816H(cc, a0, a1, a2, a3, bb0, bb1)                                 \
    asm volatile(                                                               \
        "mma.sync.aligned.m16n8k16.row.col.f16.f16.f16.f16 "                    \
        "{%0,%1}, {%2,%3,%4,%5}, {%6,%7}, {%0,%1};"                             \
        : "+r"((cc)[0]), "+r"((cc)[1])                                          \
        : "r"(a0), "r"(a1), "r"(a2), "r"(a3), "r"(bb0), "r"(bb1))

__global__ void __launch_bounds__(384, 2)
conv_min_tanh_mma(const float* __restrict__ xg, const float* __restrict__ wp,
                  const float* __restrict__ bp, float* __restrict__ outp)
{
    extern __shared__ uint32_t sm[];
    uint32_t* Bsm     = sm + W_B;
    uint32_t* bias_sm = sm + W_BIAS;
    uint32_t* planes  = sm + W_IN;

    const int tid = threadIdx.x;
    const int x0  = blockIdx.x ? (OW - 128) : 0;   // 0 or 126; overlap recomputed identically
    const int y0  = blockIdx.y * TH;
    const int b   = blockIdx.z;

    // ---- B operand, interleaved: word (pos*64+n)*8 + slot(j) ----
    // value = half2(w[n][2j][pos], w[n][2j+1][pos]); lanes j-minor -> conflict-free STS
    for (int i = tid; i < 9 * 64 * 8; i += 384) {
        int j   = i & 7;
        int n   = (i >> 3) & 63;
        int pos = i >> 9;
        int slot = (j < 4) ? (2 * j) : (2 * j - 7);
        float lo = wp[n * 144 + (2 * j) * 9 + pos];
        float hi = wp[n * 144 + (2 * j + 1) * 9 + pos];
        __half2 v = __floats2half2_rn(lo, hi);
        Bsm[(pos * 64 + n) * 8 + slot] = *reinterpret_cast<uint32_t*>(&v);
    }
    // bias pre-packed per (nt, tg): cols (nt*8 + 2tg, nt*8 + 2tg + 1)
    if (tid < 32) {
        int nt = tid >> 2, tg4 = tid & 3;
        __half2 v = __floats2half2_rn(bp[nt * 8 + 2 * tg4], bp[nt * 8 + 2 * tg4 + 1]);
        bias_sm[tid] = *reinterpret_cast<uint32_t*>(&v);
    }

    // ---- input tile, interleaved: word (r*PW + c)*8 + slot(j) ----
    const float* xb = xg + (size_t)b * (CIN * HI * WI);
    for (int i = tid; i < PR * PW * 8; i += 384) {
        int pixl = i >> 3;
        int j    = i & 7;
        int r    = pixl / PW;
        int c    = pixl - r * PW;
        int yin  = y0 + r;
        if (yin < HI) {
            int slot = (j < 4) ? (2 * j) : (2 * j - 7);
            const float* p0 = xb + (size_t)(2 * j) * (HI * WI) + yin * WI + x0 + c;
            __half2 v = __floats2half2_rn(p0[0], p0[HI * WI]);
            planes[pixl * 8 + slot] = *reinterpret_cast<uint32_t*>(&v);
        }
    }
    __syncthreads();

    const int wid  = tid >> 5;
    const int lane = tid & 31;
    const int tg   = lane & 3;     // threadID_in_group (k-pair / col selector)
    const int gid  = lane >> 2;    // groupID (pixel row selector)

    // bias registers
    uint32_t bv[8];
    #pragma unroll
    for (int nt = 0; nt < 8; nt++) bv[nt] = bias_sm[nt * 4 + tg];

    // 64 double-tiles: d -> row t = d>>2, col-segment base (d&3)*32
    for (int d = wid; d < 64; d += 12) {
        const int t = d >> 2;
        const int y = y0 + t;
        if (y >= OH) continue;
        const int cb0 = (d & 3) * 32;    // two 16-px segments: cb0, cb0+16
        const int cb1 = cb0 + 16;

        uint32_t c0[8][2], c1[8][2];
        #pragma unroll
        for (int nt = 0; nt < 8; nt++) {
            c0[nt][0] = bv[nt]; c0[nt][1] = bv[nt];
            c1[nt][0] = bv[nt]; c1[nt][1] = bv[nt];
        }

        #pragma unroll
        for (int dy = 0; dy < 3; dy++) {
            #pragma unroll
            for (int dx = 0; dx < 3; dx++) {
                const int pos = dy * 3 + dx;
                const uint32_t* abase = planes + ((t + dy) * PW + dx) * 8 + 2 * tg;
                // LDS.64: (a0,a2) and (a1,a3) per tile
                uint2 A00 = *reinterpret_cast<const uint2*>(abase + (cb0 + gid) * 8);
                uint2 A01 = *reinterpret_cast<const uint2*>(abase + (cb0 + gid + 8) * 8);
                uint2 A10 = *reinterpret_cast<const uint2*>(abase + (cb1 + gid) * 8);
                uint2 A11 = *reinterpret_cast<const uint2*>(abase + (cb1 + gid + 8) * 8);

                const uint32_t* bb = Bsm + (pos * 64 + gid) * 8 + 2 * tg;
                #pragma unroll
                for (int nt = 0; nt < 8; nt++) {
                    uint2 B = *reinterpret_cast<const uint2*>(bb + nt * 64);  // (b0,b1)
                    MMA16816H(c0[nt], A00.x, A01.x, A00.y, A01.y, B.x, B.y);
                    MMA16816H(c1[nt], A10.x, A11.x, A10.y, A11.y, B.x, B.y);
                }
            }
        }

        // epilogue: min over 64 couts, tanh(tanh), store
        #pragma unroll
        for (int ti = 0; ti < 2; ti++) {
            uint32_t (*cc)[2] = ti ? c1 : c0;
            __half2 mlo = *reinterpret_cast<__half2*>(&cc[0][0]);  // rows gid
            __half2 mhi = *reinterpret_cast<__half2*>(&cc[0][1]);  // rows gid+8
            #pragma unroll
            for (int nt = 1; nt < 8; nt++) {
                mlo = __hmin2(mlo, *reinterpret_cast<__half2*>(&cc[nt][0]));
                mhi = __hmin2(mhi, *reinterpret_cast<__half2*>(&cc[nt][1]));
            }
            uint32_t ulo = *reinterpret_cast<uint32_t*>(&mlo);
            uint32_t uhi = *reinterpret_cast<uint32_t*>(&mhi);
            uint32_t s;
            s = __shfl_xor_sync(0xFFFFFFFFu, ulo, 1);
            mlo = __hmin2(*reinterpret_cast<__half2*>(&ulo), *reinterpret_cast<__half2*>(&s));
            ulo = *reinterpret_cast<uint32_t*>(&mlo);
            s = __shfl_xor_sync(0xFFFFFFFFu, ulo, 2);
            mlo = __hmin2(*reinterpret_cast<__half2*>(&ulo), *reinterpret_cast<__half2*>(&s));
            s = __shfl_xor_sync(0xFFFFFFFFu, uhi, 1);
            mhi = __hmin2(*reinterpret_cast<__half2*>(&uhi), *reinterpret_cast<__half2*>(&s));
            uhi = *reinterpret_cast<uint32_t*>(&mhi);
            s = __shfl_xor_sync(0xFFFFFFFFu, uhi, 2);
            mhi = __hmin2(*reinterpret_cast<__half2*>(&uhi), *reinterpret_cast<__half2*>(&s));

            if (tg == 0) {
                float vlo = fminf(__low2float(mlo), __high2float(mlo));
                float vhi = fminf(__low2float(mhi), __high2float(mhi));
                vlo = tanhf(tanhf(vlo));
                vhi = tanhf(tanhf(vhi));
                const int cb = ti ? cb1 : cb0;
                float* orow = outp + ((size_t)b * OH + y) * OW + x0 + cb;
                orow[gid]     = vlo;   // pixel row gid
                orow[gid + 8] = vhi;   // pixel row gid+8
            }
        }
    }
}

// ================= launch =================
extern "C" void kernel_launch(void* const* d_in, const int* in_sizes, int n_in,
                              void* d_out, int out_size) {
    (void)in_sizes; (void)n_in; (void)out_size;
    const float* x    = (const float*)d_in[0];
    const float* w    = (const float*)d_in[1];
    const float* bias = (const float*)d_in[2];
    float* out = (float*)d_out;

    cudaFuncSetAttribute(conv_min_tanh_mma,
                         cudaFuncAttributeMaxDynamicSharedMemorySize, SMEM_BYTES);
    dim3 grid(2, 16, 64);   // x: two 128-col halves; y: 16-row tiles; z: batch
    conv_min_tanh_mma<<<grid, 384, SMEM_BYTES>>>(x, w, bias, out);
}